// round 16
// baseline (speedup 1.0000x reference)
#include <cuda_runtime.h>
#include <cuda_bf16.h>
#include <cstdint>
#include <math.h>

// Problem: N=32, LS=128, LT=64 (63 steps), VS=VT=32000, E=512, H=1024, PAD=0
#define VTG 32000
#define NSPLIT 21248   // cols [0,NSPLIT) via HMMA; [NSPLIT,32000) via f32x2

// ---- static scratch (zero-initialized at load) ----
// Packed vector layout PK: ((float4*)v)[k4*32 + n] = k values 4k4..4k4+3 of column n.
__device__ float g_emb   [4096 * 512];
__device__ float g_igates[4096 * 1024];
__device__ float g_enc_hs[4096 * 1024];     // [n][l][j] fp32 (attention ctx)
__device__ __nv_bfloat16 g_ehb[4096 * 1024];// enc_hs in bf16 (energy HMMA gemm)
__device__ float g_energy[4096 * 1024];     // [n][l][j]
__device__ float g_hT    [2][1024 * 32];    // hidden state, PK layout, ping-pong
__device__ float g_ctxT  [1024 * 32];       // context, PK layout
__device__ float g_demb  [2048 * 512];      // gathered decoder embeddings (row t*32+n)
__device__ float g_decig [2048 * 1024];     // dec emb-gates: demb @ Wih[:, :512]^T + bih
__device__ __nv_bfloat16 g_catXb[2048 * 2048];   // [h_new, ctx] bf16; rows >= 2016 stay 0
__device__ float g_catX [2048 * 2048];           // [h_new, ctx] fp32 (f32x2 branch)
__device__ __nv_bfloat16 g_Wb  [32000 * 2048];   // h2o_W in bf16
__device__ __nv_bfloat16 g_aWb [1024 * 1024];    // attn_W in bf16
__device__ unsigned g_barE, g_barD;              // grid-barrier counters

// =====================================================================
// helpers
// =====================================================================
__device__ __forceinline__ uint32_t smem_u32(const void* p) {
    uint32_t a;
    asm("{ .reg .u64 t; cvta.to.shared.u64 t, %1; cvt.u32.u64 %0, t; }" : "=r"(a) : "l"(p));
    return a;
}

// software grid barrier (gpu-scope fence -> CCTL.IVALL -> L1 coherent after)
__device__ __forceinline__ void gbar(unsigned* c, unsigned target) {
    __syncthreads();
    if (threadIdx.x == 0) {
        __threadfence();
        atomicAdd(c, 1u);
        while (*(volatile unsigned*)c < target) __nanosleep(64);
        __threadfence();
    }
    __syncthreads();
}

__device__ __forceinline__ void ldm4(uint32_t* r, uint32_t a) {
    asm volatile("ldmatrix.sync.aligned.m8n8.x4.shared.b16 {%0,%1,%2,%3}, [%4];"
        : "=r"(r[0]), "=r"(r[1]), "=r"(r[2]), "=r"(r[3]) : "r"(a));
}
__device__ __forceinline__ void mma16816(float* c, const uint32_t* a, uint32_t b0, uint32_t b1) {
    asm volatile("mma.sync.aligned.m16n8k16.row.col.f32.bf16.bf16.f32 "
        "{%0,%1,%2,%3}, {%4,%5,%6,%7}, {%8,%9}, {%0,%1,%2,%3};"
        : "+f"(c[0]), "+f"(c[1]), "+f"(c[2]), "+f"(c[3])
        : "r"(a[0]), "r"(a[1]), "r"(a[2]), "r"(a[3]), "r"(b0), "r"(b1));
}
__device__ __forceinline__ void cpa(uint32_t d, const void* s) {
    asm volatile("cp.async.cg.shared.global [%0], [%1], 16;" :: "r"(d), "l"(s));
}
#define CP_COMMIT() asm volatile("cp.async.commit_group;" ::: "memory")

// ---- f32x2 packed-FMA helpers ----
__device__ __forceinline__ unsigned long long pack_rep(float a) {
    unsigned long long r;
    asm("mov.b64 %0, {%1, %1};" : "=l"(r) : "f"(a));
    return r;
}
__device__ __forceinline__ void fma2(unsigned long long& d, unsigned long long a,
                                     unsigned long long b) {
    asm("fma.rn.f32x2 %0, %1, %2, %0;" : "+l"(d) : "l"(a), "l"(b));
}
__device__ __forceinline__ float2 u2f2(unsigned long long u) {
    float2 f;
    asm("mov.b64 {%0, %1}, %2;" : "=f"(f.x), "=f"(f.y) : "l"(u));
    return f;
}
__device__ __forceinline__ float usum(unsigned long long a, unsigned long long b) {
    float2 x = u2f2(a), y = u2f2(b);
    return x.x + x.y + y.x + y.y;
}

// =====================================================================
// small kernels
// =====================================================================
__global__ void k_init() {
    int idx = blockIdx.x * 256 + threadIdx.x;      // grid 128 -> 32768
    g_hT[0][idx] = 0.0f;
    if (idx == 0) { g_barE = 0u; g_barD = 0u; }
}

__global__ void k_gather(const int* __restrict__ src, const float* __restrict__ emb) {
    int idx = blockIdx.x * 256 + threadIdx.x;      // 4096*512
    int m = idx >> 9, e = idx & 511;
    g_emb[idx] = emb[(size_t)src[m] * 512 + e];
}

__global__ void k_gatherD(const int* __restrict__ tgt, const float* __restrict__ demb) {
    int idx = blockIdx.x * 256 + threadIdx.x;      // 2048*512
    int m = idx >> 9, e = idx & 511;
    int t = m >> 5, n = m & 31;
    g_demb[idx] = demb[(size_t)tgt[n * 64 + t] * 512 + e];
}

// fp32 -> bf16, 8 elements per thread
__global__ void k_cvt(const float* __restrict__ s, __nv_bfloat16* __restrict__ d) {
    size_t i = (size_t)blockIdx.x * 256 + threadIdx.x;
    const float4* p = (const float4*)s + i * 2;
    float4 a = p[0], b = p[1];
    __nv_bfloat162 c0 = __float22bfloat162_rn(make_float2(a.x, a.y));
    __nv_bfloat162 c1 = __float22bfloat162_rn(make_float2(a.z, a.w));
    __nv_bfloat162 c2 = __float22bfloat162_rn(make_float2(b.x, b.y));
    __nv_bfloat162 c3 = __float22bfloat162_rn(make_float2(b.z, b.w));
    uint4 o;
    o.x = *reinterpret_cast<unsigned*>(&c0);
    o.y = *reinterpret_cast<unsigned*>(&c1);
    o.z = *reinterpret_cast<unsigned*>(&c2);
    o.w = *reinterpret_cast<unsigned*>(&c3);
    ((uint4*)d)[i] = o;
}

// =====================================================================
// fp32 SGEMM (NT) with f32x2 accumulators.
// REMAP=false: C[m][n] = A·B + bias (pre-work GEMMs), C stride N.
// REMAP=true : out row (r&31)*63+(r>>5), skip r>=2016, C stride VTG,
//              column offset ncol0 (h2o tail vocab branch).
// =====================================================================
template <bool REMAP>
__global__ void __launch_bounds__(256) k_sgemm(
    const float* __restrict__ A, const float* __restrict__ B,
    const float* __restrict__ bias, float* __restrict__ C, int K, int N, int ldb,
    int ncol0)
{
    __shared__ __align__(16) float As[16][128];
    __shared__ __align__(16) float Bs[16][128];
    const int tid = threadIdx.x;
    const int m0 = blockIdx.x * 128, n0 = blockIdx.y * 128;
    const int lr = tid >> 2, lq = (tid & 3) * 4;
    const float* Ap = A + (size_t)(m0 + lr) * K + lq;
    const float* Bp = B + (size_t)(n0 + lr) * ldb + lq;
    const int ty = tid >> 4, tx = tid & 15;

    unsigned long long acc[8][4];
#pragma unroll
    for (int i = 0; i < 8; ++i)
#pragma unroll
        for (int j = 0; j < 4; ++j) acc[i][j] = 0ULL;

    for (int kt = 0; kt < K; kt += 16) {
        float4 a0 = *(const float4*)(Ap + kt);
        float4 a1 = *(const float4*)(Ap + kt + (size_t)64 * K);
        float4 b0 = *(const float4*)(Bp + kt);
        float4 b1 = *(const float4*)(Bp + kt + (size_t)64 * ldb);
        __syncthreads();
        As[lq + 0][lr] = a0.x; As[lq + 1][lr] = a0.y; As[lq + 2][lr] = a0.z; As[lq + 3][lr] = a0.w;
        As[lq + 0][lr + 64] = a1.x; As[lq + 1][lr + 64] = a1.y; As[lq + 2][lr + 64] = a1.z; As[lq + 3][lr + 64] = a1.w;
        Bs[lq + 0][lr] = b0.x; Bs[lq + 1][lr] = b0.y; Bs[lq + 2][lr] = b0.z; Bs[lq + 3][lr] = b0.w;
        Bs[lq + 0][lr + 64] = b1.x; Bs[lq + 1][lr + 64] = b1.y; Bs[lq + 2][lr + 64] = b1.z; Bs[lq + 3][lr + 64] = b1.w;
        __syncthreads();
#pragma unroll
        for (int kk = 0; kk < 16; ++kk) {
            float4 fa0 = *(const float4*)&As[kk][ty * 8];
            float4 fa1 = *(const float4*)&As[kk][ty * 8 + 4];
            ulonglong2 u0 = *(const ulonglong2*)&Bs[kk][tx * 8];
            ulonglong2 u1 = *(const ulonglong2*)&Bs[kk][tx * 8 + 4];
            float av[8] = {fa0.x, fa0.y, fa0.z, fa0.w, fa1.x, fa1.y, fa1.z, fa1.w};
#pragma unroll
            for (int i = 0; i < 8; ++i) {
                unsigned long long aa = pack_rep(av[i]);
                fma2(acc[i][0], aa, u0.x);
                fma2(acc[i][1], aa, u0.y);
                fma2(acc[i][2], aa, u1.x);
                fma2(acc[i][3], aa, u1.y);
            }
        }
    }
    const int cb = n0 + tx * 8;
#pragma unroll
    for (int i = 0; i < 8; ++i) {
        const int r = m0 + ty * 8 + i;
        float* cp;
        if (REMAP) {
            if (r >= 2016) continue;
            cp = C + (size_t)((r & 31) * 63 + (r >> 5)) * VTG + ncol0 + cb;
        } else {
            cp = C + (size_t)r * N + cb;
        }
#pragma unroll
        for (int j = 0; j < 4; ++j) {
            float2 v = u2f2(acc[i][j]);
            cp[j * 2 + 0] = v.x + bias[cb + j * 2 + 0];
            cp[j * 2 + 1] = v.y + bias[cb + j * 2 + 1];
        }
    }
}

// =====================================================================
// fused encoder RNN: 128 steps, grid 128 x 256 threads, weights in smem.
// Also emits bf16 copy of enc_hs for the HMMA energy GEMM.
// =====================================================================
__global__ void __launch_bounds__(256, 1) k_enc_rnn(
    const float* __restrict__ Whh, const float* __restrict__ bhh)
{
    __shared__ __align__(16) float wsh[8 * 1024];
    __shared__ float part[2][4][4][32];
    const int tid = threadIdx.x, lane = tid & 31, wid = tid >> 5;
    const int jg = wid >> 2, kq = wid & 3;
    const int j0 = blockIdx.x * 8 + jg * 4;

    {
        const float4* wg = (const float4*)(Whh + (size_t)blockIdx.x * 8 * 1024);
        float4* ws4 = (float4*)wsh;
#pragma unroll
        for (int i = 0; i < 8; ++i) ws4[tid + i * 256] = wg[tid + i * 256];
    }
    __syncthreads();

    const ulonglong2* w0 = (const ulonglong2*)(wsh + (jg * 4 + 0) * 1024) + kq * 64;
    const ulonglong2* w1 = (const ulonglong2*)(wsh + (jg * 4 + 1) * 1024) + kq * 64;
    const ulonglong2* w2 = (const ulonglong2*)(wsh + (jg * 4 + 2) * 1024) + kq * 64;
    const ulonglong2* w3 = (const ulonglong2*)(wsh + (jg * 4 + 3) * 1024) + kq * 64;

    for (int t = 0; t < 128; ++t) {
        const ulonglong2* x4 = (const ulonglong2*)g_hT[t & 1] + kq * 64 * 32 + lane;
        unsigned long long a0 = 0, a1 = 0, b0 = 0, b1 = 0, c0 = 0, c1 = 0, d0 = 0, d1 = 0;
#pragma unroll 8
        for (int i = 0; i < 64; ++i) {
            ulonglong2 x = x4[i * 32];
            ulonglong2 u = w0[i]; fma2(a0, x.x, u.x); fma2(a1, x.y, u.y);
            ulonglong2 v = w1[i]; fma2(b0, x.x, v.x); fma2(b1, x.y, v.y);
            ulonglong2 p = w2[i]; fma2(c0, x.x, p.x); fma2(c1, x.y, p.y);
            ulonglong2 q = w3[i]; fma2(d0, x.x, q.x); fma2(d1, x.y, q.y);
        }
        part[jg][kq][0][lane] = usum(a0, a1);
        part[jg][kq][1][lane] = usum(b0, b1);
        part[jg][kq][2][lane] = usum(c0, c1);
        part[jg][kq][3][lane] = usum(d0, d1);
        __syncthreads();
        if (kq == 0) {
#pragma unroll
            for (int r = 0; r < 4; ++r) {
                int j = j0 + r;
                float v = part[jg][0][r][lane] + part[jg][1][r][lane]
                        + part[jg][2][r][lane] + part[jg][3][r][lane];
                v = tanhf(v + g_igates[((size_t)lane * 128 + t) * 1024 + j] + bhh[j]);
                g_hT[(t + 1) & 1][(j >> 2) * 128 + lane * 4 + (j & 3)] = v;
                size_t mi = ((size_t)lane * 128 + t) * 1024 + j;
                g_enc_hs[mi] = v;
                g_ehb[mi] = __float2bfloat16_rn(v);
            }
        }
        gbar(&g_barE, (unsigned)(t + 1) * 128u);
    }
}

// =====================================================================
// fused decoder: 63 x (attention + RNN), grid 128 x 256 threads, weights smem.
// Writes catX in BOTH bf16 (HMMA branch) and fp32 (f32x2 branch).
// =====================================================================
__global__ void __launch_bounds__(256, 1) k_dec_rnn(
    const int* __restrict__ src,
    const float* __restrict__ Wih,
    const float* __restrict__ Whh, const float* __restrict__ bhh)
{
    extern __shared__ __align__(16) float dsm[];    // 8 * 2048 floats = 64KB
    __shared__ float hsh[1024];
    __shared__ float ssh[128];
    __shared__ float red;
    __shared__ float part[2][4][4][32];
    const int tid = threadIdx.x, lane = tid & 31, wid = tid >> 5;
    const int blk = blockIdx.x;
    const int jg = wid >> 2, kq = wid & 3;
    const int j0 = blk * 8 + jg * 4;
    const int j0b = blk * 8;

    {
        float4* d4 = (float4*)dsm;
#pragma unroll
        for (int i = 0; i < 8; ++i) {
            int idx = tid + i * 256;
            int jj = idx >> 8, kk = idx & 255;
            d4[jj * 512 + kk] =
                ((const float4*)(Wih + (size_t)(j0b + jj) * 1536 + 512))[kk];
            d4[jj * 512 + 256 + kk] =
                ((const float4*)(Whh + (size_t)(j0b + jj) * 1024))[kk];
        }
    }
    __syncthreads();

    const int lrow = jg * 4;
    const ulonglong2 *w0, *w1, *w2, *w3;
    if (kq < 2) {
        w0 = (const ulonglong2*)(dsm + (lrow + 0) * 2048 + kq * 512);
        w1 = (const ulonglong2*)(dsm + (lrow + 1) * 2048 + kq * 512);
        w2 = (const ulonglong2*)(dsm + (lrow + 2) * 2048 + kq * 512);
        w3 = (const ulonglong2*)(dsm + (lrow + 3) * 2048 + kq * 512);
    } else {
        w0 = (const ulonglong2*)(dsm + (lrow + 0) * 2048 + 1024 + (kq - 2) * 512);
        w1 = (const ulonglong2*)(dsm + (lrow + 1) * 2048 + 1024 + (kq - 2) * 512);
        w2 = (const ulonglong2*)(dsm + (lrow + 2) * 2048 + 1024 + (kq - 2) * 512);
        w3 = (const ulonglong2*)(dsm + (lrow + 3) * 2048 + 1024 + (kq - 2) * 512);
    }

    for (int t = 0; t < 63; ++t) {
        const float4* hin4 = (const float4*)g_hT[t & 1];

        if (blk < 32) {
            const int n = blk;
            ((float4*)hsh)[tid] = hin4[tid * 32 + n];
            __syncthreads();
            const float4* hs4 = (const float4*)hsh;
            for (int l = wid; l < 128; l += 8) {
                const float4* ep4 = (const float4*)(g_energy + ((size_t)n * 128 + l) * 1024);
                float s = 0.f;
#pragma unroll
                for (int i = 0; i < 8; ++i) {
                    float4 e = ep4[lane + 32 * i];
                    float4 hh = hs4[lane + 32 * i];
                    s += e.x * hh.x + e.y * hh.y + e.z * hh.z + e.w * hh.w;
                }
#pragma unroll
                for (int off = 16; off > 0; off >>= 1) s += __shfl_xor_sync(0xffffffffu, s, off);
                if (lane == 0) ssh[l] = (src[n * 128 + l] == 0) ? -1000000000.0f : s;
            }
            __syncthreads();
            if (wid == 0) {
                float mx = -1e30f;
                for (int l = lane; l < 128; l += 32) mx = fmaxf(mx, ssh[l]);
#pragma unroll
                for (int off = 16; off > 0; off >>= 1)
                    mx = fmaxf(mx, __shfl_xor_sync(0xffffffffu, mx, off));
                float sum = 0.f;
                for (int l = lane; l < 128; l += 32) {
                    float e = __expf(ssh[l] - mx);
                    ssh[l] = e;
                    sum += e;
                }
#pragma unroll
                for (int off = 16; off > 0; off >>= 1) sum += __shfl_xor_sync(0xffffffffu, sum, off);
                if (lane == 0) red = 1.0f / sum;
            }
            __syncthreads();
            {
                const float inv = red;
                float4 acc = make_float4(0.f, 0.f, 0.f, 0.f);
                const float4* eh = (const float4*)(g_enc_hs + (size_t)n * 128 * 1024) + tid;
#pragma unroll 4
                for (int l = 0; l < 128; ++l) {
                    float4 e = eh[(size_t)l * 256];
                    float w = ssh[l];
                    acc.x += w * e.x; acc.y += w * e.y;
                    acc.z += w * e.z; acc.w += w * e.w;
                }
                acc.x *= inv; acc.y *= inv; acc.z *= inv; acc.w *= inv;
                ((float4*)g_ctxT)[tid * 32 + n] = acc;
                *(float4*)(g_catX + ((size_t)t * 32 + n) * 2048 + 1024 + 4 * tid) = acc;
                __nv_bfloat162 p0 = __float22bfloat162_rn(make_float2(acc.x, acc.y));
                __nv_bfloat162 p1 = __float22bfloat162_rn(make_float2(acc.z, acc.w));
                uint2 pk;
                pk.x = *reinterpret_cast<unsigned*>(&p0);
                pk.y = *reinterpret_cast<unsigned*>(&p1);
                *(uint2*)(g_catXb + ((size_t)t * 32 + n) * 2048 + 1024 + 4 * tid) = pk;
            }
        }
        gbar(&g_barD, (unsigned)(2 * t + 1) * 128u);

        {
            const ulonglong2* xb = (kq < 2)
                ? ((const ulonglong2*)g_ctxT + kq * 4096 + lane)
                : ((const ulonglong2*)hin4 + (kq - 2) * 4096 + lane);
            unsigned long long a0 = 0, a1 = 0, b0 = 0, b1 = 0, c0 = 0, c1 = 0, d0 = 0, d1 = 0;
#pragma unroll 8
            for (int i = 0; i < 128; ++i) {
                ulonglong2 x = xb[i * 32];
                ulonglong2 u = w0[i]; fma2(a0, x.x, u.x); fma2(a1, x.y, u.y);
                ulonglong2 v = w1[i]; fma2(b0, x.x, v.x); fma2(b1, x.y, v.y);
                ulonglong2 p = w2[i]; fma2(c0, x.x, p.x); fma2(c1, x.y, p.y);
                ulonglong2 q = w3[i]; fma2(d0, x.x, q.x); fma2(d1, x.y, q.y);
            }
            part[jg][kq][0][lane] = usum(a0, a1);
            part[jg][kq][1][lane] = usum(b0, b1);
            part[jg][kq][2][lane] = usum(c0, c1);
            part[jg][kq][3][lane] = usum(d0, d1);
            __syncthreads();
            if (kq == 0) {
#pragma unroll
                for (int r = 0; r < 4; ++r) {
                    int j = j0 + r;
                    float v = part[jg][0][r][lane] + part[jg][1][r][lane]
                            + part[jg][2][r][lane] + part[jg][3][r][lane];
                    v = tanhf(v + g_decig[((size_t)t * 32 + lane) * 1024 + j] + bhh[j]);
                    g_hT[(t + 1) & 1][(j >> 2) * 128 + lane * 4 + (j & 3)] = v;
                    g_catX [((size_t)t * 32 + lane) * 2048 + j] = v;
                    g_catXb[((size_t)t * 32 + lane) * 2048 + j] = __float2bfloat16_rn(v);
                }
            }
        }
        gbar(&g_barD, (unsigned)(2 * t + 2) * 128u);
    }
}

// =====================================================================
// HMMA bf16 GEMM (NT) with 4-stage cp.async pipeline (prefetch distance 3):
// C[row(r), n] = A[r,:]·B[n,:] + bias[n];  K = KT*32, strides lda/ldb.
// REMAP: r -> (r&31)*63 + (r>>5), skip r>=2016 (h2o). else row=r (energy).
// =====================================================================
template <int KT, bool REMAP>
__global__ void __launch_bounds__(256, 2) k_hgemm(
    const __nv_bfloat16* __restrict__ A, int lda,
    const __nv_bfloat16* __restrict__ B, int ldb,
    const float* __restrict__ bias, float* __restrict__ C, int ldc)
{
    extern __shared__ __align__(16) uint8_t sdyn[];   // 4 stages x 20480B
    const int tid = threadIdx.x, lane = tid & 31, wid = tid >> 5;
    const int m0 = blockIdx.x * 128, n0 = blockIdx.y * 128;
    const int wm = (wid & 3) * 32, wn = (wid >> 2) * 64;

    const int row0 = tid >> 2, kc = tid & 3;
    const __nv_bfloat16* gA0 = A + (size_t)(m0 + row0) * lda + kc * 8;
    const __nv_bfloat16* gB0 = B + (size_t)(n0 + row0) * ldb + kc * 8;
    const uint32_t sb = smem_u32(sdyn);
    const uint32_t dst0 = (uint32_t)row0 * 80u + (uint32_t)kc * 16u;
    const uint32_t dst1 = dst0 + 64u * 80u;

    const uint32_t aoff = ((wm + (lane & 15)) * 40 + (lane >> 4) * 8) * 2;
    const uint32_t boff = ((wn + (lane & 7) + ((lane >> 4) << 3)) * 40 + ((lane >> 3) & 1) * 8) * 2;

    float acc[2][8][4];
#pragma unroll
    for (int i = 0; i < 2; ++i)
#pragma unroll
        for (int jx = 0; jx < 8; ++jx)
#pragma unroll
            for (int q = 0; q < 4; ++q) acc[i][jx][q] = 0.0f;

#pragma unroll
    for (int p = 0; p < 3; ++p) {
        const uint32_t base = sb + (uint32_t)p * 20480u;
        const __nv_bfloat16* pa = gA0 + p * 32;
        const __nv_bfloat16* pb = gB0 + p * 32;
        cpa(base + dst0, pa);
        cpa(base + dst1, pa + (size_t)64 * lda);
        cpa(base + 10240u + dst0, pb);
        cpa(base + 10240u + dst1, pb + (size_t)64 * ldb);
        CP_COMMIT();
    }

    for (int kt = 0; kt < KT; ++kt) {
        if (kt < KT - 3) asm volatile("cp.async.wait_group 2;" ::: "memory");
        else             asm volatile("cp.async.wait_group 0;" ::: "memory");
        __syncthreads();
        if (kt + 3 < KT) {
            const int st = (kt + 3) & 3;
            const uint32_t base = sb + (uint32_t)st * 20480u;
            const __nv_bfloat16* pa = gA0 + (kt + 3) * 32;
            const __nv_bfloat16* pb = gB0 + (kt + 3) * 32;
            cpa(base + dst0, pa);
            cpa(base + dst1, pa + (size_t)64 * lda);
            cpa(base + 10240u + dst0, pb);
            cpa(base + 10240u + dst1, pb + (size_t)64 * ldb);
            CP_COMMIT();
        }
        const uint32_t ab = sb + (uint32_t)(kt & 3) * 20480u;
        const uint32_t bb = ab + 10240u;
#pragma unroll
        for (int ks = 0; ks < 2; ++ks) {
            uint32_t af[2][4], bf[4][4];
            ldm4(af[0], ab + aoff + ks * 32);
            ldm4(af[1], ab + aoff + ks * 32 + 16 * 80);
#pragma unroll
            for (int jx = 0; jx < 4; ++jx)
                ldm4(bf[jx], bb + boff + ks * 32 + jx * 16 * 80);
#pragma unroll
            for (int i = 0; i < 2; ++i)
#pragma unroll
                for (int jx = 0; jx < 4; ++jx) {
                    mma16816(acc[i][2 * jx],     af[i], bf[jx][0], bf[jx][1]);
                    mma16816(acc[i][2 * jx + 1], af[i], bf[jx][2], bf[jx][3]);
                }
        }
    }

#pragma unroll
    for (int i = 0; i < 2; ++i) {
#pragma unroll
        for (int jx = 0; jx < 8; ++jx) {
            const int col = n0 + wn + jx * 8 + (lane & 3) * 2;
            const float b0v = bias[col], b1v = bias[col + 1];
#pragma unroll
            for (int h = 0; h < 2; ++h) {
                const int r = m0 + wm + i * 16 + (lane >> 2) + h * 8;
                float2 v = make_float2(acc[i][jx][h * 2] + b0v, acc[i][jx][h * 2 + 1] + b1v);
                if (REMAP) {
                    if (r < 2016)
                        *(float2*)(C + (size_t)((r & 31) * 63 + (r >> 5)) * ldc + col) = v;
                } else {
                    *(float2*)(C + (size_t)r * ldc + col) = v;
                }
            }
        }
    }
}

// =====================================================================
// in-place log-softmax over 32000, single-pass online, float4, 512 threads
// =====================================================================
__global__ void __launch_bounds__(512) k_logsoftmax(float* __restrict__ out)
{
    __shared__ float sm_[16], ss_[16];
    float4* p = (float4*)(out + (size_t)blockIdx.x * VTG);   // 8000 float4
    const int tid = threadIdx.x, lane = tid & 31, warp = tid >> 5;

    float m = -1e30f, s = 0.0f;
    for (int i = tid; i < 8000; i += 512) {
        float4 x = p[i];
        float xm = fmaxf(fmaxf(x.x, x.y), fmaxf(x.z, x.w));
        if (xm > m) { s = s * __expf(m - xm); m = xm; }
        s += __expf(x.x - m) + __expf(x.y - m) + __expf(x.z - m) + __expf(x.w - m);
    }
#pragma unroll
    for (int off = 16; off > 0; off >>= 1) {
        float mo = __shfl_xor_sync(0xffffffffu, m, off);
        float so = __shfl_xor_sync(0xffffffffu, s, off);
        float m2 = fmaxf(m, mo);
        s = s * __expf(m - m2) + so * __expf(mo - m2);
        m = m2;
    }
    if (lane == 0) { sm_[warp] = m; ss_[warp] = s; }
    __syncthreads();
    float M = sm_[0], S = ss_[0];
#pragma unroll
    for (int w = 1; w < 16; ++w) {
        float m2 = fmaxf(M, sm_[w]);
        S = S * __expf(M - m2) + ss_[w] * __expf(sm_[w] - m2);
        M = m2;
    }
    const float lse = M + logf(S);
    for (int i = tid; i < 8000; i += 512) {
        float4 x = p[i];
        x.x -= lse; x.y -= lse; x.z -= lse; x.w -= lse;
        p[i] = x;
    }
}

// =====================================================================
extern "C" void kernel_launch(void* const* d_in, const int* in_sizes, int n_in,
                              void* d_out, int out_size)
{
    const int*   src       = (const int*)  d_in[0];
    const int*   tgt       = (const int*)  d_in[1];
    const float* enc_embed = (const float*)d_in[2];
    const float* enc_Wih   = (const float*)d_in[3];
    const float* enc_bih   = (const float*)d_in[4];
    const float* enc_Whh   = (const float*)d_in[5];
    const float* enc_bhh   = (const float*)d_in[6];
    const float* dec_embed = (const float*)d_in[7];
    const float* attn_W    = (const float*)d_in[8];
    const float* attn_b    = (const float*)d_in[9];
    const float* dec_Wih   = (const float*)d_in[10];
    const float* dec_bih   = (const float*)d_in[11];
    const float* dec_Whh   = (const float*)d_in[12];
    const float* dec_bhh   = (const float*)d_in[13];
    const float* h2o_W     = (const float*)d_in[14];
    const float* h2o_b     = (const float*)d_in[15];
    float* out = (float*)d_out;

    float* d_emb    = nullptr; cudaGetSymbolAddress((void**)&d_emb,    g_emb);
    float* d_igates = nullptr; cudaGetSymbolAddress((void**)&d_igates, g_igates);
    float* d_energy = nullptr; cudaGetSymbolAddress((void**)&d_energy, g_energy);
    float* d_demb   = nullptr; cudaGetSymbolAddress((void**)&d_demb,   g_demb);
    float* d_decig  = nullptr; cudaGetSymbolAddress((void**)&d_decig,  g_decig);
    float* d_catX   = nullptr; cudaGetSymbolAddress((void**)&d_catX,   g_catX);
    __nv_bfloat16* d_catXb = nullptr; cudaGetSymbolAddress((void**)&d_catXb, g_catXb);
    __nv_bfloat16* d_Wb    = nullptr; cudaGetSymbolAddress((void**)&d_Wb,    g_Wb);
    __nv_bfloat16* d_ehb   = nullptr; cudaGetSymbolAddress((void**)&d_ehb,   g_ehb);
    __nv_bfloat16* d_aWb   = nullptr; cudaGetSymbolAddress((void**)&d_aWb,   g_aWb);

    static bool init_done = false;
    static cudaStream_t s2 = nullptr;
    static cudaEvent_t evFork = nullptr, evJoin = nullptr;
    if (!init_done) {
        cudaFuncSetAttribute(k_hgemm<64, true>,
                             cudaFuncAttributeMaxDynamicSharedMemorySize, 81920);
        cudaFuncSetAttribute(k_hgemm<32, false>,
                             cudaFuncAttributeMaxDynamicSharedMemorySize, 81920);
        cudaFuncSetAttribute(k_dec_rnn, cudaFuncAttributeMaxDynamicSharedMemorySize, 65536);
        cudaStreamCreateWithFlags(&s2, cudaStreamNonBlocking);
        cudaEventCreateWithFlags(&evFork, cudaEventDisableTiming);
        cudaEventCreateWithFlags(&evJoin, cudaEventDisableTiming);
        init_done = true;
    }

    // pre-work
    k_init<<<128, 256>>>();
    k_cvt<<<32000, 256>>>(h2o_W, d_Wb);
    k_gather<<<8192, 256>>>(src, enc_embed);
    k_cvt<<<512, 256>>>(attn_W, d_aWb);
    k_sgemm<false><<<dim3(32, 8), 256>>>(d_emb, enc_Wih, enc_bih, d_igates,
                                         512, 1024, 512, 0);
    k_gatherD<<<4096, 256>>>(tgt, dec_embed);
    k_sgemm<false><<<dim3(16, 8), 256>>>(d_demb, dec_Wih, dec_bih, d_decig,
                                         512, 1024, 1536, 0);

    // fused encoder RNN (128 steps, weights in smem; also writes bf16 enc_hs)
    k_enc_rnn<<<128, 256>>>(enc_Whh, enc_bhh);

    // energy GEMM on HMMA (4096x1024x1024, bf16 in / fp32 out + attn_b)
    k_hgemm<32, false><<<dim3(32, 8), 256, 81920>>>(
        d_ehb, 1024, d_aWb, 1024, attn_b, d_energy, 1024);

    // fused decoder (63 x attention+RNN, weights in smem)
    k_dec_rnn<<<128, 256, 65536>>>(src, dec_Wih, dec_Whh, dec_bhh);

    // ---- fork: h2o GEMM split across tensor (HMMA) and fma (f32x2) pipes ----
    cudaEventRecord(evFork, 0);
    cudaStreamWaitEvent(s2, evFork, 0);

    // branch A (main stream): cols [0, 21248) on HMMA
    k_hgemm<64, true><<<dim3(16, 166), 256, 81920>>>(
        d_catXb, 2048, d_Wb, 2048, h2o_b, out, VTG);

    // branch B (stream s2): cols [21248, 32000) on f32x2 FMA pipe
    k_sgemm<true><<<dim3(16, 84), 256, 0, s2>>>(
        d_catX, h2o_W + (size_t)NSPLIT * 2048, h2o_b + NSPLIT, out,
        2048, VTG, 2048, NSPLIT);

    cudaEventRecord(evJoin, s2);
    cudaStreamWaitEvent(0, evJoin, 0);

    // log-softmax over vocab, in place
    k_logsoftmax<<<2016, 512>>>(out);
}

// round 17
// speedup vs baseline: 1.4483x; 1.4483x over previous
#include <cuda_runtime.h>
#include <cuda_bf16.h>
#include <cstdint>
#include <math.h>

// Problem: N=32, LS=128, LT=64 (63 steps), VS=VT=32000, E=512, H=1024, PAD=0
#define VTG 32000

// ---- static scratch (zero-initialized at load) ----
// Packed vector layout PK: ((float4*)v)[k4*32 + n] = k values 4k4..4k4+3 of column n.
__device__ float g_emb   [4096 * 512];
__device__ float g_igates[4096 * 1024];
__device__ float g_enc_hs[4096 * 1024];     // [n][l][j] fp32 (attention ctx)
__device__ __nv_bfloat16 g_ehb[4096 * 1024];// enc_hs in bf16 (energy HMMA gemm)
__device__ float g_energy[4096 * 1024];     // [n][l][j]
__device__ float g_hT    [2][1024 * 32];    // hidden state, PK layout, ping-pong
__device__ float g_ctxT  [1024 * 32];       // context, PK layout
__device__ float g_demb  [2048 * 512];      // gathered decoder embeddings (row t*32+n)
__device__ float g_decig [2048 * 1024];     // dec emb-gates: demb @ Wih[:, :512]^T + bih
__device__ __nv_bfloat16 g_catXb[2048 * 2048];   // [h_new, ctx] bf16; rows >= 2016 stay 0
__device__ __nv_bfloat16 g_Wb  [32000 * 2048];   // h2o_W in bf16
__device__ __nv_bfloat16 g_aWb [1024 * 1024];    // attn_W in bf16
__device__ unsigned g_barE, g_barD;              // grid-barrier counters

// =====================================================================
// helpers
// =====================================================================
__device__ __forceinline__ uint32_t smem_u32(const void* p) {
    uint32_t a;
    asm("{ .reg .u64 t; cvta.to.shared.u64 t, %1; cvt.u32.u64 %0, t; }" : "=r"(a) : "l"(p));
    return a;
}

// software grid barrier (gpu-scope fence -> CCTL.IVALL -> L1 coherent after)
__device__ __forceinline__ void gbar(unsigned* c, unsigned target) {
    __syncthreads();
    if (threadIdx.x == 0) {
        __threadfence();
        atomicAdd(c, 1u);
        while (*(volatile unsigned*)c < target) __nanosleep(64);
        __threadfence();
    }
    __syncthreads();
}

__device__ __forceinline__ void ldm4(uint32_t* r, uint32_t a) {
    asm volatile("ldmatrix.sync.aligned.m8n8.x4.shared.b16 {%0,%1,%2,%3}, [%4];"
        : "=r"(r[0]), "=r"(r[1]), "=r"(r[2]), "=r"(r[3]) : "r"(a));
}
__device__ __forceinline__ void mma16816(float* c, const uint32_t* a, uint32_t b0, uint32_t b1) {
    asm volatile("mma.sync.aligned.m16n8k16.row.col.f32.bf16.bf16.f32 "
        "{%0,%1,%2,%3}, {%4,%5,%6,%7}, {%8,%9}, {%0,%1,%2,%3};"
        : "+f"(c[0]), "+f"(c[1]), "+f"(c[2]), "+f"(c[3])
        : "r"(a[0]), "r"(a[1]), "r"(a[2]), "r"(a[3]), "r"(b0), "r"(b1));
}
__device__ __forceinline__ void cpa(uint32_t d, const void* s) {
    asm volatile("cp.async.cg.shared.global [%0], [%1], 16;" :: "r"(d), "l"(s));
}
#define CP_COMMIT() asm volatile("cp.async.commit_group;" ::: "memory")

// ---- f32x2 packed-FMA helpers ----
__device__ __forceinline__ unsigned long long pack_rep(float a) {
    unsigned long long r;
    asm("mov.b64 %0, {%1, %1};" : "=l"(r) : "f"(a));
    return r;
}
__device__ __forceinline__ void fma2(unsigned long long& d, unsigned long long a,
                                     unsigned long long b) {
    asm("fma.rn.f32x2 %0, %1, %2, %0;" : "+l"(d) : "l"(a), "l"(b));
}
__device__ __forceinline__ float2 u2f2(unsigned long long u) {
    float2 f;
    asm("mov.b64 {%0, %1}, %2;" : "=f"(f.x), "=f"(f.y) : "l"(u));
    return f;
}
__device__ __forceinline__ float usum(unsigned long long a, unsigned long long b) {
    float2 x = u2f2(a), y = u2f2(b);
    return x.x + x.y + y.x + y.y;
}

// =====================================================================
// small kernels
// =====================================================================
__global__ void k_init() {
    int idx = blockIdx.x * 256 + threadIdx.x;      // grid 128 -> 32768
    g_hT[0][idx] = 0.0f;
    if (idx == 0) { g_barE = 0u; g_barD = 0u; }
}

__global__ void k_gather(const int* __restrict__ src, const float* __restrict__ emb) {
    int idx = blockIdx.x * 256 + threadIdx.x;      // 4096*512
    int m = idx >> 9, e = idx & 511;
    g_emb[idx] = emb[(size_t)src[m] * 512 + e];
}

__global__ void k_gatherD(const int* __restrict__ tgt, const float* __restrict__ demb) {
    int idx = blockIdx.x * 256 + threadIdx.x;      // 2048*512
    int m = idx >> 9, e = idx & 511;
    int t = m >> 5, n = m & 31;
    g_demb[idx] = demb[(size_t)tgt[n * 64 + t] * 512 + e];
}

// fp32 -> bf16, 8 elements per thread
__global__ void k_cvt(const float* __restrict__ s, __nv_bfloat16* __restrict__ d) {
    size_t i = (size_t)blockIdx.x * 256 + threadIdx.x;
    const float4* p = (const float4*)s + i * 2;
    float4 a = p[0], b = p[1];
    __nv_bfloat162 c0 = __float22bfloat162_rn(make_float2(a.x, a.y));
    __nv_bfloat162 c1 = __float22bfloat162_rn(make_float2(a.z, a.w));
    __nv_bfloat162 c2 = __float22bfloat162_rn(make_float2(b.x, b.y));
    __nv_bfloat162 c3 = __float22bfloat162_rn(make_float2(b.z, b.w));
    uint4 o;
    o.x = *reinterpret_cast<unsigned*>(&c0);
    o.y = *reinterpret_cast<unsigned*>(&c1);
    o.z = *reinterpret_cast<unsigned*>(&c2);
    o.w = *reinterpret_cast<unsigned*>(&c3);
    ((uint4*)d)[i] = o;
}

// =====================================================================
// fp32 SGEMM (NT): C[m][n] = A[m,:]·B[n, :K] + bias[n], B row stride ldb
// =====================================================================
__global__ void __launch_bounds__(256) k_sgemm(
    const float* __restrict__ A, const float* __restrict__ B,
    const float* __restrict__ bias, float* __restrict__ C, int K, int N, int ldb)
{
    __shared__ __align__(16) float As[16][128];
    __shared__ __align__(16) float Bs[16][128];
    const int tid = threadIdx.x;
    const int m0 = blockIdx.x * 128, n0 = blockIdx.y * 128;
    const int lr = tid >> 2, lq = (tid & 3) * 4;
    const float* Ap = A + (size_t)(m0 + lr) * K + lq;
    const float* Bp = B + (size_t)(n0 + lr) * ldb + lq;
    const int ty = tid >> 4, tx = tid & 15;

    unsigned long long acc[8][4];
#pragma unroll
    for (int i = 0; i < 8; ++i)
#pragma unroll
        for (int j = 0; j < 4; ++j) acc[i][j] = 0ULL;

    for (int kt = 0; kt < K; kt += 16) {
        float4 a0 = *(const float4*)(Ap + kt);
        float4 a1 = *(const float4*)(Ap + kt + (size_t)64 * K);
        float4 b0 = *(const float4*)(Bp + kt);
        float4 b1 = *(const float4*)(Bp + kt + (size_t)64 * ldb);
        __syncthreads();
        As[lq + 0][lr] = a0.x; As[lq + 1][lr] = a0.y; As[lq + 2][lr] = a0.z; As[lq + 3][lr] = a0.w;
        As[lq + 0][lr + 64] = a1.x; As[lq + 1][lr + 64] = a1.y; As[lq + 2][lr + 64] = a1.z; As[lq + 3][lr + 64] = a1.w;
        Bs[lq + 0][lr] = b0.x; Bs[lq + 1][lr] = b0.y; Bs[lq + 2][lr] = b0.z; Bs[lq + 3][lr] = b0.w;
        Bs[lq + 0][lr + 64] = b1.x; Bs[lq + 1][lr + 64] = b1.y; Bs[lq + 2][lr + 64] = b1.z; Bs[lq + 3][lr + 64] = b1.w;
        __syncthreads();
#pragma unroll
        for (int kk = 0; kk < 16; ++kk) {
            float4 fa0 = *(const float4*)&As[kk][ty * 8];
            float4 fa1 = *(const float4*)&As[kk][ty * 8 + 4];
            ulonglong2 u0 = *(const ulonglong2*)&Bs[kk][tx * 8];
            ulonglong2 u1 = *(const ulonglong2*)&Bs[kk][tx * 8 + 4];
            float av[8] = {fa0.x, fa0.y, fa0.z, fa0.w, fa1.x, fa1.y, fa1.z, fa1.w};
#pragma unroll
            for (int i = 0; i < 8; ++i) {
                unsigned long long aa = pack_rep(av[i]);
                fma2(acc[i][0], aa, u0.x);
                fma2(acc[i][1], aa, u0.y);
                fma2(acc[i][2], aa, u1.x);
                fma2(acc[i][3], aa, u1.y);
            }
        }
    }
    const int cb = n0 + tx * 8;
#pragma unroll
    for (int i = 0; i < 8; ++i) {
        float* cp = C + (size_t)(m0 + ty * 8 + i) * N + cb;
#pragma unroll
        for (int j = 0; j < 4; ++j) {
            float2 v = u2f2(acc[i][j]);
            cp[j * 2 + 0] = v.x + bias[cb + j * 2 + 0];
            cp[j * 2 + 1] = v.y + bias[cb + j * 2 + 1];
        }
    }
}

// =====================================================================
// fused encoder RNN: 128 steps, grid 128 x 256 threads, weights in smem.
// Also emits bf16 copy of enc_hs for the HMMA energy GEMM.
// =====================================================================
__global__ void __launch_bounds__(256, 1) k_enc_rnn(
    const float* __restrict__ Whh, const float* __restrict__ bhh)
{
    __shared__ __align__(16) float wsh[8 * 1024];
    __shared__ float part[2][4][4][32];
    const int tid = threadIdx.x, lane = tid & 31, wid = tid >> 5;
    const int jg = wid >> 2, kq = wid & 3;
    const int j0 = blockIdx.x * 8 + jg * 4;

    {
        const float4* wg = (const float4*)(Whh + (size_t)blockIdx.x * 8 * 1024);
        float4* ws4 = (float4*)wsh;
#pragma unroll
        for (int i = 0; i < 8; ++i) ws4[tid + i * 256] = wg[tid + i * 256];
    }
    __syncthreads();

    const ulonglong2* w0 = (const ulonglong2*)(wsh + (jg * 4 + 0) * 1024) + kq * 64;
    const ulonglong2* w1 = (const ulonglong2*)(wsh + (jg * 4 + 1) * 1024) + kq * 64;
    const ulonglong2* w2 = (const ulonglong2*)(wsh + (jg * 4 + 2) * 1024) + kq * 64;
    const ulonglong2* w3 = (const ulonglong2*)(wsh + (jg * 4 + 3) * 1024) + kq * 64;

    for (int t = 0; t < 128; ++t) {
        const ulonglong2* x4 = (const ulonglong2*)g_hT[t & 1] + kq * 64 * 32 + lane;
        unsigned long long a0 = 0, a1 = 0, b0 = 0, b1 = 0, c0 = 0, c1 = 0, d0 = 0, d1 = 0;
#pragma unroll 8
        for (int i = 0; i < 64; ++i) {
            ulonglong2 x = x4[i * 32];
            ulonglong2 u = w0[i]; fma2(a0, x.x, u.x); fma2(a1, x.y, u.y);
            ulonglong2 v = w1[i]; fma2(b0, x.x, v.x); fma2(b1, x.y, v.y);
            ulonglong2 p = w2[i]; fma2(c0, x.x, p.x); fma2(c1, x.y, p.y);
            ulonglong2 q = w3[i]; fma2(d0, x.x, q.x); fma2(d1, x.y, q.y);
        }
        part[jg][kq][0][lane] = usum(a0, a1);
        part[jg][kq][1][lane] = usum(b0, b1);
        part[jg][kq][2][lane] = usum(c0, c1);
        part[jg][kq][3][lane] = usum(d0, d1);
        __syncthreads();
        if (kq == 0) {
#pragma unroll
            for (int r = 0; r < 4; ++r) {
                int j = j0 + r;
                float v = part[jg][0][r][lane] + part[jg][1][r][lane]
                        + part[jg][2][r][lane] + part[jg][3][r][lane];
                v = tanhf(v + g_igates[((size_t)lane * 128 + t) * 1024 + j] + bhh[j]);
                g_hT[(t + 1) & 1][(j >> 2) * 128 + lane * 4 + (j & 3)] = v;
                size_t mi = ((size_t)lane * 128 + t) * 1024 + j;
                g_enc_hs[mi] = v;
                g_ehb[mi] = __float2bfloat16_rn(v);
            }
        }
        gbar(&g_barE, (unsigned)(t + 1) * 128u);
    }
}

// =====================================================================
// fused decoder: 63 x (attention + RNN), grid 128 x 256 threads, weights smem
// =====================================================================
__global__ void __launch_bounds__(256, 1) k_dec_rnn(
    const int* __restrict__ src,
    const float* __restrict__ Wih,
    const float* __restrict__ Whh, const float* __restrict__ bhh)
{
    extern __shared__ __align__(16) float dsm[];    // 8 * 2048 floats = 64KB
    __shared__ float hsh[1024];
    __shared__ float ssh[128];
    __shared__ float red;
    __shared__ float part[2][4][4][32];
    const int tid = threadIdx.x, lane = tid & 31, wid = tid >> 5;
    const int blk = blockIdx.x;
    const int jg = wid >> 2, kq = wid & 3;
    const int j0 = blk * 8 + jg * 4;
    const int j0b = blk * 8;

    {
        float4* d4 = (float4*)dsm;
#pragma unroll
        for (int i = 0; i < 8; ++i) {
            int idx = tid + i * 256;
            int jj = idx >> 8, kk = idx & 255;
            d4[jj * 512 + kk] =
                ((const float4*)(Wih + (size_t)(j0b + jj) * 1536 + 512))[kk];
            d4[jj * 512 + 256 + kk] =
                ((const float4*)(Whh + (size_t)(j0b + jj) * 1024))[kk];
        }
    }
    __syncthreads();

    const int lrow = jg * 4;
    const ulonglong2 *w0, *w1, *w2, *w3;
    if (kq < 2) {
        w0 = (const ulonglong2*)(dsm + (lrow + 0) * 2048 + kq * 512);
        w1 = (const ulonglong2*)(dsm + (lrow + 1) * 2048 + kq * 512);
        w2 = (const ulonglong2*)(dsm + (lrow + 2) * 2048 + kq * 512);
        w3 = (const ulonglong2*)(dsm + (lrow + 3) * 2048 + kq * 512);
    } else {
        w0 = (const ulonglong2*)(dsm + (lrow + 0) * 2048 + 1024 + (kq - 2) * 512);
        w1 = (const ulonglong2*)(dsm + (lrow + 1) * 2048 + 1024 + (kq - 2) * 512);
        w2 = (const ulonglong2*)(dsm + (lrow + 2) * 2048 + 1024 + (kq - 2) * 512);
        w3 = (const ulonglong2*)(dsm + (lrow + 3) * 2048 + 1024 + (kq - 2) * 512);
    }

    for (int t = 0; t < 63; ++t) {
        const float4* hin4 = (const float4*)g_hT[t & 1];

        if (blk < 32) {
            const int n = blk;
            ((float4*)hsh)[tid] = hin4[tid * 32 + n];
            __syncthreads();
            const float4* hs4 = (const float4*)hsh;
            for (int l = wid; l < 128; l += 8) {
                const float4* ep4 = (const float4*)(g_energy + ((size_t)n * 128 + l) * 1024);
                float s = 0.f;
#pragma unroll
                for (int i = 0; i < 8; ++i) {
                    float4 e = ep4[lane + 32 * i];
                    float4 hh = hs4[lane + 32 * i];
                    s += e.x * hh.x + e.y * hh.y + e.z * hh.z + e.w * hh.w;
                }
#pragma unroll
                for (int off = 16; off > 0; off >>= 1) s += __shfl_xor_sync(0xffffffffu, s, off);
                if (lane == 0) ssh[l] = (src[n * 128 + l] == 0) ? -1000000000.0f : s;
            }
            __syncthreads();
            if (wid == 0) {
                float mx = -1e30f;
                for (int l = lane; l < 128; l += 32) mx = fmaxf(mx, ssh[l]);
#pragma unroll
                for (int off = 16; off > 0; off >>= 1)
                    mx = fmaxf(mx, __shfl_xor_sync(0xffffffffu, mx, off));
                float sum = 0.f;
                for (int l = lane; l < 128; l += 32) {
                    float e = __expf(ssh[l] - mx);
                    ssh[l] = e;
                    sum += e;
                }
#pragma unroll
                for (int off = 16; off > 0; off >>= 1) sum += __shfl_xor_sync(0xffffffffu, sum, off);
                if (lane == 0) red = 1.0f / sum;
            }
            __syncthreads();
            {
                const float inv = red;
                float4 acc = make_float4(0.f, 0.f, 0.f, 0.f);
                const float4* eh = (const float4*)(g_enc_hs + (size_t)n * 128 * 1024) + tid;
#pragma unroll 4
                for (int l = 0; l < 128; ++l) {
                    float4 e = eh[(size_t)l * 256];
                    float w = ssh[l];
                    acc.x += w * e.x; acc.y += w * e.y;
                    acc.z += w * e.z; acc.w += w * e.w;
                }
                acc.x *= inv; acc.y *= inv; acc.z *= inv; acc.w *= inv;
                ((float4*)g_ctxT)[tid * 32 + n] = acc;
                __nv_bfloat162 p0 = __float22bfloat162_rn(make_float2(acc.x, acc.y));
                __nv_bfloat162 p1 = __float22bfloat162_rn(make_float2(acc.z, acc.w));
                uint2 pk;
                pk.x = *reinterpret_cast<unsigned*>(&p0);
                pk.y = *reinterpret_cast<unsigned*>(&p1);
                *(uint2*)(g_catXb + ((size_t)t * 32 + n) * 2048 + 1024 + 4 * tid) = pk;
            }
        }
        gbar(&g_barD, (unsigned)(2 * t + 1) * 128u);

        {
            const ulonglong2* xb = (kq < 2)
                ? ((const ulonglong2*)g_ctxT + kq * 4096 + lane)
                : ((const ulonglong2*)hin4 + (kq - 2) * 4096 + lane);
            unsigned long long a0 = 0, a1 = 0, b0 = 0, b1 = 0, c0 = 0, c1 = 0, d0 = 0, d1 = 0;
#pragma unroll 8
            for (int i = 0; i < 128; ++i) {
                ulonglong2 x = xb[i * 32];
                ulonglong2 u = w0[i]; fma2(a0, x.x, u.x); fma2(a1, x.y, u.y);
                ulonglong2 v = w1[i]; fma2(b0, x.x, v.x); fma2(b1, x.y, v.y);
                ulonglong2 p = w2[i]; fma2(c0, x.x, p.x); fma2(c1, x.y, p.y);
                ulonglong2 q = w3[i]; fma2(d0, x.x, q.x); fma2(d1, x.y, q.y);
            }
            part[jg][kq][0][lane] = usum(a0, a1);
            part[jg][kq][1][lane] = usum(b0, b1);
            part[jg][kq][2][lane] = usum(c0, c1);
            part[jg][kq][3][lane] = usum(d0, d1);
            __syncthreads();
            if (kq == 0) {
#pragma unroll
                for (int r = 0; r < 4; ++r) {
                    int j = j0 + r;
                    float v = part[jg][0][r][lane] + part[jg][1][r][lane]
                            + part[jg][2][r][lane] + part[jg][3][r][lane];
                    v = tanhf(v + g_decig[((size_t)t * 32 + lane) * 1024 + j] + bhh[j]);
                    g_hT[(t + 1) & 1][(j >> 2) * 128 + lane * 4 + (j & 3)] = v;
                    g_catXb[((size_t)t * 32 + lane) * 2048 + j] = __float2bfloat16_rn(v);
                }
            }
        }
        gbar(&g_barD, (unsigned)(2 * t + 2) * 128u);
    }
}

// =====================================================================
// HMMA bf16 GEMM (NT) with 4-stage cp.async pipeline (prefetch distance 3):
// C[row(r), n] = A[r,:]·B[n,:] + bias[n];  K = KT*32, strides lda/ldb.
// REMAP: r -> (r&31)*63 + (r>>5), skip r>=2016 (h2o). else row=r (energy).
// =====================================================================
template <int KT, bool REMAP>
__global__ void __launch_bounds__(256, 2) k_hgemm(
    const __nv_bfloat16* __restrict__ A, int lda,
    const __nv_bfloat16* __restrict__ B, int ldb,
    const float* __restrict__ bias, float* __restrict__ C, int ldc)
{
    extern __shared__ __align__(16) uint8_t sdyn[];   // 4 stages x 20480B
    const int tid = threadIdx.x, lane = tid & 31, wid = tid >> 5;
    const int m0 = blockIdx.x * 128, n0 = blockIdx.y * 128;
    const int wm = (wid & 3) * 32, wn = (wid >> 2) * 64;

    const int row0 = tid >> 2, kc = tid & 3;
    const __nv_bfloat16* gA0 = A + (size_t)(m0 + row0) * lda + kc * 8;
    const __nv_bfloat16* gB0 = B + (size_t)(n0 + row0) * ldb + kc * 8;
    const uint32_t sb = smem_u32(sdyn);
    const uint32_t dst0 = (uint32_t)row0 * 80u + (uint32_t)kc * 16u;
    const uint32_t dst1 = dst0 + 64u * 80u;

    const uint32_t aoff = ((wm + (lane & 15)) * 40 + (lane >> 4) * 8) * 2;
    const uint32_t boff = ((wn + (lane & 7) + ((lane >> 4) << 3)) * 40 + ((lane >> 3) & 1) * 8) * 2;

    float acc[2][8][4];
#pragma unroll
    for (int i = 0; i < 2; ++i)
#pragma unroll
        for (int jx = 0; jx < 8; ++jx)
#pragma unroll
            for (int q = 0; q < 4; ++q) acc[i][jx][q] = 0.0f;

#pragma unroll
    for (int p = 0; p < 3; ++p) {
        const uint32_t base = sb + (uint32_t)p * 20480u;
        const __nv_bfloat16* pa = gA0 + p * 32;
        const __nv_bfloat16* pb = gB0 + p * 32;
        cpa(base + dst0, pa);
        cpa(base + dst1, pa + (size_t)64 * lda);
        cpa(base + 10240u + dst0, pb);
        cpa(base + 10240u + dst1, pb + (size_t)64 * ldb);
        CP_COMMIT();
    }

    for (int kt = 0; kt < KT; ++kt) {
        if (kt < KT - 3) asm volatile("cp.async.wait_group 2;" ::: "memory");
        else             asm volatile("cp.async.wait_group 0;" ::: "memory");
        __syncthreads();
        if (kt + 3 < KT) {
            const int st = (kt + 3) & 3;
            const uint32_t base = sb + (uint32_t)st * 20480u;
            const __nv_bfloat16* pa = gA0 + (kt + 3) * 32;
            const __nv_bfloat16* pb = gB0 + (kt + 3) * 32;
            cpa(base + dst0, pa);
            cpa(base + dst1, pa + (size_t)64 * lda);
            cpa(base + 10240u + dst0, pb);
            cpa(base + 10240u + dst1, pb + (size_t)64 * ldb);
            CP_COMMIT();
        }
        const uint32_t ab = sb + (uint32_t)(kt & 3) * 20480u;
        const uint32_t bb = ab + 10240u;
#pragma unroll
        for (int ks = 0; ks < 2; ++ks) {
            uint32_t af[2][4], bf[4][4];
            ldm4(af[0], ab + aoff + ks * 32);
            ldm4(af[1], ab + aoff + ks * 32 + 16 * 80);
#pragma unroll
            for (int jx = 0; jx < 4; ++jx)
                ldm4(bf[jx], bb + boff + ks * 32 + jx * 16 * 80);
#pragma unroll
            for (int i = 0; i < 2; ++i)
#pragma unroll
                for (int jx = 0; jx < 4; ++jx) {
                    mma16816(acc[i][2 * jx],     af[i], bf[jx][0], bf[jx][1]);
                    mma16816(acc[i][2 * jx + 1], af[i], bf[jx][2], bf[jx][3]);
                }
        }
    }

#pragma unroll
    for (int i = 0; i < 2; ++i) {
#pragma unroll
        for (int jx = 0; jx < 8; ++jx) {
            const int col = n0 + wn + jx * 8 + (lane & 3) * 2;
            const float b0v = bias[col], b1v = bias[col + 1];
#pragma unroll
            for (int h = 0; h < 2; ++h) {
                const int r = m0 + wm + i * 16 + (lane >> 2) + h * 8;
                float2 v = make_float2(acc[i][jx][h * 2] + b0v, acc[i][jx][h * 2 + 1] + b1v);
                if (REMAP) {
                    if (r < 2016)
                        *(float2*)(C + (size_t)((r & 31) * 63 + (r >> 5)) * ldc + col) = v;
                } else {
                    *(float2*)(C + (size_t)r * ldc + col) = v;
                }
            }
        }
    }
}

// =====================================================================
// in-place log-softmax over 32000, single-pass online, float4, 512 threads
// =====================================================================
__global__ void __launch_bounds__(512) k_logsoftmax(float* __restrict__ out)
{
    __shared__ float sm_[16], ss_[16];
    float4* p = (float4*)(out + (size_t)blockIdx.x * VTG);   // 8000 float4
    const int tid = threadIdx.x, lane = tid & 31, warp = tid >> 5;

    float m = -1e30f, s = 0.0f;
    for (int i = tid; i < 8000; i += 512) {
        float4 x = p[i];
        float xm = fmaxf(fmaxf(x.x, x.y), fmaxf(x.z, x.w));
        if (xm > m) { s = s * __expf(m - xm); m = xm; }
        s += __expf(x.x - m) + __expf(x.y - m) + __expf(x.z - m) + __expf(x.w - m);
    }
#pragma unroll
    for (int off = 16; off > 0; off >>= 1) {
        float mo = __shfl_xor_sync(0xffffffffu, m, off);
        float so = __shfl_xor_sync(0xffffffffu, s, off);
        float m2 = fmaxf(m, mo);
        s = s * __expf(m - m2) + so * __expf(mo - m2);
        m = m2;
    }
    if (lane == 0) { sm_[warp] = m; ss_[warp] = s; }
    __syncthreads();
    float M = sm_[0], S = ss_[0];
#pragma unroll
    for (int w = 1; w < 16; ++w) {
        float m2 = fmaxf(M, sm_[w]);
        S = S * __expf(M - m2) + ss_[w] * __expf(sm_[w] - m2);
        M = m2;
    }
    const float lse = M + logf(S);
    for (int i = tid; i < 8000; i += 512) {
        float4 x = p[i];
        x.x -= lse; x.y -= lse; x.z -= lse; x.w -= lse;
        p[i] = x;
    }
}

// =====================================================================
extern "C" void kernel_launch(void* const* d_in, const int* in_sizes, int n_in,
                              void* d_out, int out_size)
{
    const int*   src       = (const int*)  d_in[0];
    const int*   tgt       = (const int*)  d_in[1];
    const float* enc_embed = (const float*)d_in[2];
    const float* enc_Wih   = (const float*)d_in[3];
    const float* enc_bih   = (const float*)d_in[4];
    const float* enc_Whh   = (const float*)d_in[5];
    const float* enc_bhh   = (const float*)d_in[6];
    const float* dec_embed = (const float*)d_in[7];
    const float* attn_W    = (const float*)d_in[8];
    const float* attn_b    = (const float*)d_in[9];
    const float* dec_Wih   = (const float*)d_in[10];
    const float* dec_bih   = (const float*)d_in[11];
    const float* dec_Whh   = (const float*)d_in[12];
    const float* dec_bhh   = (const float*)d_in[13];
    const float* h2o_W     = (const float*)d_in[14];
    const float* h2o_b     = (const float*)d_in[15];
    float* out = (float*)d_out;

    float* d_emb    = nullptr; cudaGetSymbolAddress((void**)&d_emb,    g_emb);
    float* d_igates = nullptr; cudaGetSymbolAddress((void**)&d_igates, g_igates);
    float* d_energy = nullptr; cudaGetSymbolAddress((void**)&d_energy, g_energy);
    float* d_demb   = nullptr; cudaGetSymbolAddress((void**)&d_demb,   g_demb);
    float* d_decig  = nullptr; cudaGetSymbolAddress((void**)&d_decig,  g_decig);
    __nv_bfloat16* d_catXb = nullptr; cudaGetSymbolAddress((void**)&d_catXb, g_catXb);
    __nv_bfloat16* d_Wb    = nullptr; cudaGetSymbolAddress((void**)&d_Wb,    g_Wb);
    __nv_bfloat16* d_ehb   = nullptr; cudaGetSymbolAddress((void**)&d_ehb,   g_ehb);
    __nv_bfloat16* d_aWb   = nullptr; cudaGetSymbolAddress((void**)&d_aWb,   g_aWb);

    static bool init_done = false;
    static cudaStream_t s2 = nullptr;
    static cudaEvent_t evFork = nullptr, evPre = nullptr;
    if (!init_done) {
        cudaFuncSetAttribute(k_hgemm<64, true>,
                             cudaFuncAttributeMaxDynamicSharedMemorySize, 81920);
        cudaFuncSetAttribute(k_hgemm<32, false>,
                             cudaFuncAttributeMaxDynamicSharedMemorySize, 81920);
        cudaFuncSetAttribute(k_dec_rnn, cudaFuncAttributeMaxDynamicSharedMemorySize, 65536);
        cudaStreamCreateWithFlags(&s2, cudaStreamNonBlocking);
        cudaEventCreateWithFlags(&evFork, cudaEventDisableTiming);
        cudaEventCreateWithFlags(&evPre, cudaEventDisableTiming);
        init_done = true;
    }

    // fork: independent pre-work (weight conversions + decoder embedding
    // gates) runs on s2, overlapping the encoder path on the main stream.
    cudaEventRecord(evFork, 0);
    cudaStreamWaitEvent(s2, evFork, 0);

    // s2: h2o_W -> bf16, attn_W -> bf16, decoder embeddings + emb-gates GEMM
    k_cvt<<<32000, 256, 0, s2>>>(h2o_W, d_Wb);
    k_cvt<<<512, 256, 0, s2>>>(attn_W, d_aWb);
    k_gatherD<<<4096, 256, 0, s2>>>(tgt, dec_embed);
    k_sgemm<<<dim3(16, 8), 256, 0, s2>>>(d_demb, dec_Wih, dec_bih, d_decig,
                                         512, 1024, 1536);
    cudaEventRecord(evPre, s2);

    // main: encoder path
    k_init<<<128, 256>>>();
    k_gather<<<8192, 256>>>(src, enc_embed);
    k_sgemm<<<dim3(32, 8), 256>>>(d_emb, enc_Wih, enc_bih, d_igates, 512, 1024, 512);
    k_enc_rnn<<<128, 256>>>(enc_Whh, enc_bhh);

    // join: energy GEMM needs attn_W bf16; decoder needs decig; h2o needs Wb
    cudaStreamWaitEvent(0, evPre, 0);

    // energy GEMM on HMMA (4096x1024x1024, bf16 in / fp32 out + attn_b)
    k_hgemm<32, false><<<dim3(32, 8), 256, 81920>>>(
        d_ehb, 1024, d_aWb, 1024, attn_b, d_energy, 1024);

    // fused decoder (63 x attention+RNN, weights in smem)
    k_dec_rnn<<<128, 256, 65536>>>(src, dec_Wih, dec_Whh, dec_bhh);

    // h2o GEMM on HMMA tensor cores (2016x32000x2048, 4-stage pipeline)
    k_hgemm<64, true><<<dim3(16, 250), 256, 81920>>>(
        d_catXb, 2048, d_Wb, 2048, h2o_b, out, VTG);

    // log-softmax over vocab, in place
    k_logsoftmax<<<2016, 512>>>(out);
}